// round 3
// baseline (speedup 1.0000x reference)
#include <cuda_runtime.h>
#include <math_constants.h>

// SPP: out = concat([x, maxpool5(x), maxpool9(x), maxpool13(x)], axis=C)
// x: (16, 512, 64, 64) f32 ; out: (16, 2048, 64, 64) f32
// Uses SPPF identity: pool9 = pool5(pool5(x)), pool13 = pool5(pool9).
// Each 5x5 pool is separable: 5-wide horizontal then 5-tall vertical,
// done in shared memory ping-pong buffers, float4 vectorized.

#define NCH 512
#define HW  64
#define PLANE 4096          // 64*64 floats
#define PLANE4 1024         // in float4 units
#define ROW4 16             // float4s per row

__global__ __launch_bounds__(256, 2)
void spp_kernel(const float* __restrict__ x, float* __restrict__ out) {
    __shared__ float4 sA[PLANE4];
    __shared__ float4 sB[PLANE4];

    const int tid   = threadIdx.x;
    const int plane = blockIdx.x;          // n*512 + c
    const int n     = plane >> 9;
    const int c     = plane & 511;

    const float4* __restrict__ xp4 =
        (const float4*)(x + (size_t)plane * PLANE);

    // ---- load plane + passthrough copy (chunk 0) ----
    float4* out0 = (float4*)(out + ((size_t)(n * 2048 + c)) * PLANE);
    #pragma unroll
    for (int i = 0; i < 4; i++) {
        const int g = tid + i * 256;
        float4 v = xp4[g];
        sA[g] = v;
        out0[g] = v;
    }
    __syncthreads();

    // ---- chain of three 5x5 pools ----
    #pragma unroll
    for (int j = 1; j <= 3; j++) {
        // horizontal window-5 max: sA -> sB
        #pragma unroll
        for (int i = 0; i < 4; i++) {
            const int g    = tid + i * 256;
            const int colg = g & (ROW4 - 1);
            float4 m = sA[g];
            float am2, am1, a4, a5;
            if (colg > 0) { float4 l = sA[g - 1]; am2 = l.z; am1 = l.w; }
            else          { am2 = -CUDART_INF_F;  am1 = -CUDART_INF_F; }
            if (colg < ROW4 - 1) { float4 r = sA[g + 1]; a4 = r.x; a5 = r.y; }
            else                 { a4 = -CUDART_INF_F;   a5 = -CUDART_INF_F; }

            const float p12 = fmaxf(m.y, m.z);
            float4 o;
            o.x = fmaxf(fmaxf(am2, am1), fmaxf(m.x, p12));
            o.y = fmaxf(fmaxf(am1, m.x), fmaxf(p12, m.w));
            o.z = fmaxf(fmaxf(m.x, p12), fmaxf(m.w, a4));
            o.w = fmaxf(fmaxf(p12, m.w), fmaxf(a4,  a5));
            sB[g] = o;
        }
        __syncthreads();

        // vertical window-5 max: sB -> sA, and write chunk j to gmem
        float4* outj = (float4*)(out + ((size_t)(n * 2048 + j * 512 + c)) * PLANE);
        #pragma unroll
        for (int i = 0; i < 4; i++) {
            const int g = tid + i * 256;
            const int r = g >> 4;
            float4 v = sB[g];
            #pragma unroll
            for (int dr = -2; dr <= 2; dr++) {
                if (dr == 0) continue;
                const int rr = r + dr;
                if (rr >= 0 && rr < HW) {
                    float4 t = sB[g + dr * ROW4];
                    v.x = fmaxf(v.x, t.x);
                    v.y = fmaxf(v.y, t.y);
                    v.z = fmaxf(v.z, t.z);
                    v.w = fmaxf(v.w, t.w);
                }
            }
            sA[g] = v;
            outj[g] = v;
        }
        __syncthreads();
    }
}

extern "C" void kernel_launch(void* const* d_in, const int* in_sizes, int n_in,
                              void* d_out, int out_size) {
    const float* x = (const float*)d_in[0];
    float* out = (float*)d_out;
    spp_kernel<<<16 * NCH, 256>>>(x, out);
}

// round 7
// speedup vs baseline: 1.3503x; 1.3503x over previous
#include <cuda_runtime.h>
#include <math_constants.h>

// SPP: out = concat([x, maxpool5(x), maxpool9(x), maxpool13(x)], axis=C)
// x: (16, 512, 64, 64) f32 ; out: (16, 2048, 64, 64) f32
// SPPF identity: pool9 = pool5(pool5(x)), pool13 = pool5(pool9).
// Each 5x5 pool is separable. Thread layout: each thread owns one float4
// column (col4) x 4 consecutive rows, so the vertical pass keeps its own
// h-results in registers and only reads a 4-row halo from shared.

#define NCH 512
#define HW  64
#define PLANE 4096          // 64*64 floats
#define PLANE4 1024         // in float4 units
#define ROW4 16             // float4s per row

__device__ __forceinline__ float4 f4max(float4 a, float4 b) {
    return make_float4(fmaxf(a.x, b.x), fmaxf(a.y, b.y),
                       fmaxf(a.z, b.z), fmaxf(a.w, b.w));
}

__global__ __launch_bounds__(256, 2)
void spp_kernel(const float* __restrict__ x, float* __restrict__ out) {
    __shared__ float4 sA[PLANE4];   // current field
    __shared__ float4 sB[PLANE4];   // h-pass result (halo exchange)

    const int tid   = threadIdx.x;
    const int col4  = tid & (ROW4 - 1);     // 0..15
    const int rb    = (tid >> 4) << 2;      // row base: 0,4,...,60
    const int plane = blockIdx.x;           // n*512 + c
    const int n     = plane >> 9;
    const int c     = plane & 511;

    const float4 NEG4 = make_float4(-CUDART_INF_F, -CUDART_INF_F,
                                    -CUDART_INF_F, -CUDART_INF_F);

    const float4* __restrict__ xp4 =
        (const float4*)(x + (size_t)plane * PLANE);

    // ---- load plane + passthrough copy (chunk 0) ----
    float4* out0 = (float4*)(out + ((size_t)(n * 2048 + c)) * PLANE);
    #pragma unroll
    for (int i = 0; i < 4; i++) {
        const int g = (rb + i) * ROW4 + col4;
        float4 v = xp4[g];
        sA[g] = v;
        out0[g] = v;
    }
    __syncthreads();

    // ---- chain of three 5x5 pools ----
    #pragma unroll
    for (int j = 1; j <= 3; j++) {
        // horizontal window-5 max: sA -> registers hv[] (+ sB for halo)
        float4 hv[4];
        #pragma unroll
        for (int i = 0; i < 4; i++) {
            const int g = (rb + i) * ROW4 + col4;
            float4 m = sA[g];
            float am2, am1, a4, a5;
            if (col4 > 0) { float4 l = sA[g - 1]; am2 = l.z; am1 = l.w; }
            else          { am2 = -CUDART_INF_F;  am1 = -CUDART_INF_F; }
            if (col4 < ROW4 - 1) { float4 r = sA[g + 1]; a4 = r.x; a5 = r.y; }
            else                 { a4 = -CUDART_INF_F;   a5 = -CUDART_INF_F; }

            const float p12 = fmaxf(m.y, m.z);
            float4 o;
            o.x = fmaxf(fmaxf(am2, am1), fmaxf(m.x, p12));
            o.y = fmaxf(fmaxf(am1, m.x), fmaxf(p12, m.w));
            o.z = fmaxf(fmaxf(m.x, p12), fmaxf(m.w, a4));
            o.w = fmaxf(fmaxf(p12, m.w), fmaxf(a4,  a5));
            hv[i] = o;
            sB[g] = o;
        }
        __syncthreads();

        // vertical window-5 max: registers + 4-row halo from sB
        // h-rows needed: rb-2 .. rb+5 -> vv[0..7]
        float4 vv[8];
        vv[2] = hv[0]; vv[3] = hv[1]; vv[4] = hv[2]; vv[5] = hv[3];
        if (rb > 0) {
            vv[0] = sB[(rb - 2) * ROW4 + col4];
            vv[1] = sB[(rb - 1) * ROW4 + col4];
        } else {
            vv[0] = NEG4; vv[1] = NEG4;
        }
        if (rb < HW - 4) {
            vv[6] = sB[(rb + 4) * ROW4 + col4];
            vv[7] = sB[(rb + 5) * ROW4 + col4];
        } else {
            vv[6] = NEG4; vv[7] = NEG4;
        }

        // shared pairwise maxes: p[k] = max(vv[k], vv[k+1])
        float4 p0 = f4max(vv[0], vv[1]);
        float4 p1 = f4max(vv[1], vv[2]);
        float4 p2 = f4max(vv[2], vv[3]);
        float4 p3 = f4max(vv[3], vv[4]);
        float4 p4 = f4max(vv[4], vv[5]);
        float4 p5 = f4max(vv[5], vv[6]);

        float4 o0 = f4max(f4max(p0, p2), vv[4]);
        float4 o1 = f4max(f4max(p1, p3), vv[5]);
        float4 o2 = f4max(f4max(p2, p4), vv[6]);
        float4 o3 = f4max(f4max(p3, p5), vv[7]);

        float4* outj = (float4*)(out + ((size_t)(n * 2048 + j * 512 + c)) * PLANE);
        const int g0 = rb * ROW4 + col4;
        outj[g0 + 0 * ROW4] = o0;
        outj[g0 + 1 * ROW4] = o1;
        outj[g0 + 2 * ROW4] = o2;
        outj[g0 + 3 * ROW4] = o3;
        if (j != 3) {
            sA[g0 + 0 * ROW4] = o0;
            sA[g0 + 1 * ROW4] = o1;
            sA[g0 + 2 * ROW4] = o2;
            sA[g0 + 3 * ROW4] = o3;
            __syncthreads();
        }
    }
}

extern "C" void kernel_launch(void* const* d_in, const int* in_sizes, int n_in,
                              void* d_out, int out_size) {
    const float* x = (const float*)d_in[0];
    float* out = (float*)d_out;
    spp_kernel<<<16 * NCH, 256>>>(x, out);
}

// round 11
// speedup vs baseline: 1.3853x; 1.0259x over previous
#include <cuda_runtime.h>
#include <math_constants.h>

// SPP: out = concat([x, maxpool5(x), maxpool9(x), maxpool13(x)], axis=C)
// x: (16, 512, 64, 64) f32 ; out: (16, 2048, 64, 64) f32
// SPPF identity: pool9 = pool5(pool5(x)), pool13 = pool5(pool9).
// Each 5x5 pool is separable. Thread layout: one float4-column (col4) x 4
// consecutive rows per thread, held in registers across the whole pool chain.
// Horizontal pass uses warp shuffles (neighbor float4s live in lanes +-1);
// shared memory is used ONLY to exchange the 4-row vertical halo (16 KB).

#define NCH 512
#define HW  64
#define PLANE 4096          // 64*64 floats
#define PLANE4 1024         // in float4 units
#define ROW4 16             // float4s per row

__device__ __forceinline__ float4 f4max(float4 a, float4 b) {
    return make_float4(fmaxf(a.x, b.x), fmaxf(a.y, b.y),
                       fmaxf(a.z, b.z), fmaxf(a.w, b.w));
}

__global__ __launch_bounds__(256, 4)
void spp_kernel(const float* __restrict__ x, float* __restrict__ out) {
    __shared__ float4 sB[PLANE4];   // h-pass field (vertical halo exchange)

    const int tid   = threadIdx.x;
    const int col4  = tid & (ROW4 - 1);     // 0..15
    const int rb    = (tid >> 4) << 2;      // row base: 0,4,...,60
    const int plane = blockIdx.x;           // n*512 + c
    const int n     = plane >> 9;
    const int c     = plane & 511;

    const float4 NEG4 = make_float4(-CUDART_INF_F, -CUDART_INF_F,
                                    -CUDART_INF_F, -CUDART_INF_F);
    const unsigned FULL = 0xffffffffu;

    const float4* __restrict__ xp4 =
        (const float4*)(x + (size_t)plane * PLANE);
    float4* out0 = (float4*)(out + ((size_t)(n * 2048 + c)) * PLANE);

    const int g0 = rb * ROW4 + col4;

    // ---- load plane into registers + passthrough copy (chunk 0) ----
    float4 v[4];
    #pragma unroll
    for (int i = 0; i < 4; i++) {
        v[i] = xp4[g0 + i * ROW4];
        out0[g0 + i * ROW4] = v[i];
    }

    // ---- chain of three 5x5 pools ----
    #pragma unroll
    for (int j = 1; j <= 3; j++) {
        // horizontal window-5 max via warp shuffle: v[] -> hv[] (registers)
        float4 hv[4];
        #pragma unroll
        for (int i = 0; i < 4; i++) {
            float4 m = v[i];
            float lz = __shfl_up_sync(FULL, m.z, 1);
            float lw = __shfl_up_sync(FULL, m.w, 1);
            float rx = __shfl_down_sync(FULL, m.x, 1);
            float ry = __shfl_down_sync(FULL, m.y, 1);
            if (col4 == 0)        { lz = -CUDART_INF_F; lw = -CUDART_INF_F; }
            if (col4 == ROW4 - 1) { rx = -CUDART_INF_F; ry = -CUDART_INF_F; }

            const float p12 = fmaxf(m.y, m.z);
            hv[i].x = fmaxf(fmaxf(lz, lw),  fmaxf(m.x, p12));
            hv[i].y = fmaxf(fmaxf(lw, m.x), fmaxf(p12, m.w));
            hv[i].z = fmaxf(fmaxf(m.x, p12), fmaxf(m.w, rx));
            hv[i].w = fmaxf(fmaxf(p12, m.w), fmaxf(rx,  ry));
        }

        // publish h-field for vertical halo
        #pragma unroll
        for (int i = 0; i < 4; i++) sB[g0 + i * ROW4] = hv[i];
        __syncthreads();

        // vertical window-5 max: registers + 4-row halo from sB
        float4 vv0, vv1, vv6, vv7;
        if (rb > 0) {
            vv0 = sB[g0 - 2 * ROW4];
            vv1 = sB[g0 - 1 * ROW4];
        } else { vv0 = NEG4; vv1 = NEG4; }
        if (rb < HW - 4) {
            vv6 = sB[g0 + 4 * ROW4];
            vv7 = sB[g0 + 5 * ROW4];
        } else { vv6 = NEG4; vv7 = NEG4; }

        float4 p0 = f4max(vv0,   vv1);
        float4 p1 = f4max(vv1,   hv[0]);
        float4 p2 = f4max(hv[0], hv[1]);
        float4 p3 = f4max(hv[1], hv[2]);
        float4 p4 = f4max(hv[2], hv[3]);
        float4 p5 = f4max(hv[3], vv6);

        v[0] = f4max(f4max(p0, p2), hv[2]);
        v[1] = f4max(f4max(p1, p3), hv[3]);
        v[2] = f4max(f4max(p2, p4), vv6);
        v[3] = f4max(f4max(p3, p5), vv7);

        float4* outj = (float4*)(out + ((size_t)(n * 2048 + j * 512 + c)) * PLANE);
        #pragma unroll
        for (int i = 0; i < 4; i++) outj[g0 + i * ROW4] = v[i];

        // next pool overwrites sB; halo readers must be done first
        if (j != 3) __syncthreads();
    }
}

extern "C" void kernel_launch(void* const* d_in, const int* in_sizes, int n_in,
                              void* d_out, int out_size) {
    const float* x = (const float*)d_in[0];
    float* out = (float*)d_out;
    spp_kernel<<<16 * NCH, 256>>>(x, out);
}